// round 11
// baseline (speedup 1.0000x reference)
#include <cuda_runtime.h>
#include <math.h>

// ---------------------------------------------------------------------------
// VariationalDecoder: 168-step GRU decoder, B=1024, H=512, XP=256.
// 128 CTAs x 256 threads, TB=8 rows/CTA, TWO gate-columns per thread.
// f-broadcast LDS cost per FMA halved vs R9 (the measured binder).
// Gate weights (col-pair,k2)-packed float4, double-buffered in registers.
// GEMM1 weights k4-packed float4 with an 8-k2-deep register pipeline.
// ---------------------------------------------------------------------------

#define L_STEPS 168
#define BATCH   1024
#define HDIM    512
#define XPDIM   256
#define XLDIM   64
#define XEDIM   16
#define FEAT    592
#define G3      1536
#define TB      8
#define NCTA    (BATCH / TB)  // 128
#define NT      256
#define OUTL    169
#define OUTC    24
#define OUT_ROW (OUTL * OUTC)           // 4056
#define NMU     ((size_t)BATCH * OUT_ROW)
#define NK2_G   384                      // gate k2 blocks: 128 (ih) + 256 (hh)

// gate weights, combined ih|hh, padded by 4 k2 for prefetch overrun:
// [k2][gate][cpair] float4 = {c0k0, c0k1, c1k0, c1k1}
__device__ float4 g_WgP4[(NK2_G + 4) * 3 * 256];
// GEMM1 weights: [q=148][n=256] float4 = {k4q..k4q+3 for col n}
__device__ float4 g_WtbP4[148 * 256];
// heads: [k2=256][o=48] float2
__device__ float2 g_WhP[256 * 48];

typedef unsigned long long u64;

__device__ __forceinline__ u64 ffma2(u64 a, u64 b, u64 c) {
    u64 d;
    asm("fma.rn.f32x2 %0, %1, %2, %3;" : "=l"(d) : "l"(a), "l"(b), "l"(c));
    return d;
}
__device__ __forceinline__ u64 splat2(float x) {
    u64 d;
    asm("mov.b64 %0, {%1, %1};" : "=l"(d) : "f"(x));
    return d;
}
__device__ __forceinline__ float2 unpack2(u64 v) {
    float2 f;
    asm("mov.b64 {%0, %1}, %2;" : "=f"(f.x), "=f"(f.y) : "l"(v));
    return f;
}
__device__ __forceinline__ float sigm(float x) { return 1.0f / (1.0f + expf(-x)); }

// ---------------------------------------------------------------------------
// Prep: pack weights (once per launch)
// ---------------------------------------------------------------------------
__global__ void prep_kernel(const float* __restrict__ Wih,
                            const float* __restrict__ Whh,
                            const float* __restrict__ Wmu,
                            const float* __restrict__ Wlv,
                            const float* __restrict__ Wtb) {
    int stride = gridDim.x * blockDim.x;
    int tid = blockIdx.x * blockDim.x + threadIdx.x;
    for (int idx = tid; idx < (NK2_G + 4) * 3 * 256; idx += stride) {
        int k2 = idx / 768, rem = idx % 768;
        int g = rem / 256, cp = rem % 256;
        float4 v = make_float4(0.f, 0.f, 0.f, 0.f);
        if (k2 < 128) {                         // Wih [1536,256]
            int k0 = 2 * k2, j0 = g * 512 + 2 * cp;
            v = make_float4(Wih[j0 * XPDIM + k0],       Wih[j0 * XPDIM + k0 + 1],
                            Wih[(j0 + 1) * XPDIM + k0], Wih[(j0 + 1) * XPDIM + k0 + 1]);
        } else if (k2 < NK2_G) {                // Whh [1536,512]
            int k0 = 2 * (k2 - 128), j0 = g * 512 + 2 * cp;
            v = make_float4(Whh[j0 * HDIM + k0],       Whh[j0 * HDIM + k0 + 1],
                            Whh[(j0 + 1) * HDIM + k0], Whh[(j0 + 1) * HDIM + k0 + 1]);
        }
        g_WgP4[idx] = v;
    }
    for (int idx = tid; idx < 148 * 256; idx += stride) {
        int q = idx / 256, n = idx % 256;       // Wtb [592,256]
        g_WtbP4[idx] = make_float4(Wtb[(4 * q) * XPDIM + n], Wtb[(4 * q + 1) * XPDIM + n],
                                   Wtb[(4 * q + 2) * XPDIM + n], Wtb[(4 * q + 3) * XPDIM + n]);
    }
    for (int idx = tid; idx < 256 * 48; idx += stride) {
        int k2 = idx / 48, o = idx % 48;
        const float* Wh = (o < 24) ? (Wmu + o * HDIM) : (Wlv + (o - 24) * HDIM);
        g_WhP[idx] = make_float2(Wh[2 * k2], Wh[2 * k2 + 1]);
    }
}

// ---------------------------------------------------------------------------
// 16 FFMA2 for one gate, one k2, two columns
// ---------------------------------------------------------------------------
__device__ __forceinline__ void gate_fma(float4 wv,
                                         ulonglong2 A0, ulonglong2 B0,
                                         ulonglong2 A1, ulonglong2 B1,
                                         u64 (&ac)[2][4]) {
    u64 w;
    w = splat2(wv.x);   // col0, k0
    ac[0][0] = ffma2(A0.x, w, ac[0][0]); ac[0][1] = ffma2(A0.y, w, ac[0][1]);
    ac[0][2] = ffma2(B0.x, w, ac[0][2]); ac[0][3] = ffma2(B0.y, w, ac[0][3]);
    w = splat2(wv.y);   // col0, k1
    ac[0][0] = ffma2(A1.x, w, ac[0][0]); ac[0][1] = ffma2(A1.y, w, ac[0][1]);
    ac[0][2] = ffma2(B1.x, w, ac[0][2]); ac[0][3] = ffma2(B1.y, w, ac[0][3]);
    w = splat2(wv.z);   // col1, k0
    ac[1][0] = ffma2(A0.x, w, ac[1][0]); ac[1][1] = ffma2(A0.y, w, ac[1][1]);
    ac[1][2] = ffma2(B0.x, w, ac[1][2]); ac[1][3] = ffma2(B0.y, w, ac[1][3]);
    w = splat2(wv.w);   // col1, k1
    ac[1][0] = ffma2(A1.x, w, ac[1][0]); ac[1][1] = ffma2(A1.y, w, ac[1][1]);
    ac[1][2] = ffma2(B1.x, w, ac[1][2]); ac[1][3] = ffma2(B1.y, w, ac[1][3]);
}

// process one 2-k2 block (4 k rows) for 3 gates, 2 columns
__device__ __forceinline__ void proc2(const float*& f, const float4 (&wb)[2][3],
                                      u64 (&aR)[2][4], u64 (&aZ)[2][4],
                                      u64 (&aN)[2][4]) {
#pragma unroll
    for (int q = 0; q < 2; ++q) {
        ulonglong2 A0 = *reinterpret_cast<const ulonglong2*>(f);
        ulonglong2 B0 = *reinterpret_cast<const ulonglong2*>(f + 4);
        ulonglong2 A1 = *reinterpret_cast<const ulonglong2*>(f + 8);
        ulonglong2 B1 = *reinterpret_cast<const ulonglong2*>(f + 12);
        f += 16;
        gate_fma(wb[q][0], A0, B0, A1, B1, aR);
        gate_fma(wb[q][1], A0, B0, A1, B1, aZ);
        gate_fma(wb[q][2], A0, B0, A1, B1, aN);
    }
}

// GEMM1: one float4 of weights = 4 k rows for this thread's column
__device__ __forceinline__ void proc_q(const float*& f, float4 wq, u64 (&a)[4]) {
    float wv[4] = {wq.x, wq.y, wq.z, wq.w};
#pragma unroll
    for (int kk = 0; kk < 4; ++kk) {
        ulonglong2 A = *reinterpret_cast<const ulonglong2*>(f);
        ulonglong2 B = *reinterpret_cast<const ulonglong2*>(f + 4);
        f += 8;
        u64 w = splat2(wv[kk]);
        a[0] = ffma2(A.x, w, a[0]); a[1] = ffma2(A.y, w, a[1]);
        a[2] = ffma2(B.x, w, a[2]); a[3] = ffma2(B.y, w, a[3]);
    }
}

// ---------------------------------------------------------------------------
// Heads: 192 threads split-K (4 x 64 k2), 48 threads reduce + store
// ---------------------------------------------------------------------------
__device__ __forceinline__ void do_heads(const float* featT, float* red,
                                         float* __restrict__ out, int b0, int tstep,
                                         const float* __restrict__ bmu,
                                         const float* __restrict__ blv) {
    int t = threadIdx.x;
    __syncthreads();   // h_new visible in featT
    if (t < 192) {
        int o = t % 48;
        int p = t / 48;                    // k partition 0..3
        u64 a0 = 0, a1 = 0, a2 = 0, a3 = 0;
        const float2* w = g_WhP + (p * 64) * 48 + o;
        const float* f = featT + (p * 128) * 8;
#pragma unroll 4
        for (int k2 = 0; k2 < 64; ++k2) {
            ulonglong2 A0 = *reinterpret_cast<const ulonglong2*>(f);
            ulonglong2 B0 = *reinterpret_cast<const ulonglong2*>(f + 4);
            ulonglong2 A1 = *reinterpret_cast<const ulonglong2*>(f + 8);
            ulonglong2 B1 = *reinterpret_cast<const ulonglong2*>(f + 12);
            float2 wv = *w;
            u64 w0 = splat2(wv.x), w1 = splat2(wv.y);
            a0 = ffma2(A0.x, w0, a0); a1 = ffma2(A0.y, w0, a1);
            a2 = ffma2(B0.x, w0, a2); a3 = ffma2(B0.y, w0, a3);
            a0 = ffma2(A1.x, w1, a0); a1 = ffma2(A1.y, w1, a1);
            a2 = ffma2(B1.x, w1, a2); a3 = ffma2(B1.y, w1, a3);
            f += 16; w += 48;
        }
        u64* rp = reinterpret_cast<u64*>(red + t * 8);
        rp[0] = a0; rp[1] = a1; rp[2] = a2; rp[3] = a3;
    }
    __syncthreads();
    if (t < 48) {
        float bias = (t < 24) ? bmu[t] : blv[t - 24];
        float* obase = (t < 24) ? (out + (size_t)tstep * 24 + t)
                                : (out + NMU + (size_t)tstep * 24 + (t - 24));
#pragma unroll
        for (int r = 0; r < 8; ++r) {
            float s = bias;
#pragma unroll
            for (int p = 0; p < 4; ++p)
                s += red[(p * 48 + t) * 8 + r];
            obase[(size_t)(b0 + r) * OUT_ROW] = s;
        }
    }
}

// ---------------------------------------------------------------------------
// Main persistent kernel
// ---------------------------------------------------------------------------
__global__ void __launch_bounds__(NT, 1)
decoder_kernel(const float* __restrict__ xl, const float* __restrict__ xe,
               const float* __restrict__ z,
               const float* __restrict__ bih, const float* __restrict__ bhh,
               const float* __restrict__ bmu, const float* __restrict__ blv,
               const float* __restrict__ btb,
               float* __restrict__ out) {
    __shared__ __align__(16) float featT[FEAT * 8];  // [k][r], k<HDIM is h
    __shared__ __align__(16) float xpT[XPDIM * 8];   // x_prime transposed
    __shared__ __align__(16) float red[192 * 8];     // heads partials

    const int t  = threadIdx.x;                      // 0..255
    const int b0 = blockIdx.x * TB;
    const int c0 = 2 * t;                            // columns c0, c0+1

    // fused biases (r,z: b_ih+b_hh; n: separate)
    float2 v1, v2;
    v1 = *reinterpret_cast<const float2*>(bih + c0);
    v2 = *reinterpret_cast<const float2*>(bhh + c0);
    const float brz_r0 = v1.x + v2.x, brz_r1 = v1.y + v2.y;
    v1 = *reinterpret_cast<const float2*>(bih + 512 + c0);
    v2 = *reinterpret_cast<const float2*>(bhh + 512 + c0);
    const float brz_z0 = v1.x + v2.x, brz_z1 = v1.y + v2.y;
    v1 = *reinterpret_cast<const float2*>(bih + 1024 + c0);
    v2 = *reinterpret_cast<const float2*>(bhh + 1024 + c0);
    const float bn_i0 = v1.x, bn_i1 = v1.y;
    const float bn_h0 = v2.x, bn_h1 = v2.y;
    const float btb_n = btb[t];

    // h <- z_latent (transposed into featT)
#pragma unroll
    for (int m = 0; m < 16; ++m) {
        int idx = t + NT * m;           // 0..4095
        int r = idx >> 9, k = idx & 511;
        featT[k * 8 + r] = z[(size_t)(b0 + r) * HDIM + k];
    }

    do_heads(featT, red, out, b0, 0, bmu, blv);      // t = 0 heads from z

    for (int step = 0; step < L_STEPS; ++step) {
        // ---- load x_l_t, x_ext_t into featT tail -------------------------
#pragma unroll
        for (int m = 0; m < 2; ++m) {
            int idx = t + NT * m;       // 0..511
            int r = idx >> 6, i = idx & 63;
            featT[(HDIM + i) * 8 + r] =
                xl[((size_t)(b0 + r) * L_STEPS + step) * XLDIM + i];
        }
        if (t < 128) {
            int r = t >> 4, i = t & 15;
            featT[(HDIM + XLDIM + i) * 8 + r] =
                xe[((size_t)(b0 + r) * L_STEPS + step) * XEDIM + i];
        }
        __syncthreads();

        // ---- GEMM1 (full-K per thread, 8-k2-deep pipeline) ----------------
        {
            u64 a[4];
            {
                u64 bb = splat2(btb_n);
                a[0] = bb; a[1] = bb; a[2] = bb; a[3] = bb;
            }
            const float4* w = g_WtbP4 + t;
            const float* f = featT;
            float4 wA[4], wB[4];
#pragma unroll
            for (int i = 0; i < 4; ++i) wA[i] = w[i * 256];
            w += 4 * 256;
#pragma unroll 1
            for (int it = 0; it < 18; ++it) {
#pragma unroll
                for (int i = 0; i < 4; ++i) wB[i] = w[i * 256];
                w += 4 * 256;
#pragma unroll
                for (int i = 0; i < 4; ++i) proc_q(f, wA[i], a);
#pragma unroll
                for (int i = 0; i < 4; ++i) wA[i] = w[i * 256];
                w += 4 * 256;
#pragma unroll
                for (int i = 0; i < 4; ++i) proc_q(f, wB[i], a);
            }
#pragma unroll
            for (int i = 0; i < 4; ++i) proc_q(f, wA[i], a);   // block 36 (last)
#pragma unroll
            for (int j = 0; j < 4; ++j) {
                float2 vv = unpack2(a[j]);
                xpT[t * 8 + 2 * j]     = tanhf(vv.x);
                xpT[t * 8 + 2 * j + 1] = tanhf(vv.y);
            }
        }
        __syncthreads();

        // ---- GRU gate GEMMs: cols c0,c0+1; fused r/z accumulators ---------
        u64 aR[2][4], aZ[2][4], aNi[2][4], aNh[2][4];
        {
            u64 r0 = splat2(brz_r0), r1 = splat2(brz_r1);
            u64 z0 = splat2(brz_z0), z1 = splat2(brz_z1);
            u64 n0 = splat2(bn_i0),  n1 = splat2(bn_i1);
#pragma unroll
            for (int p = 0; p < 4; ++p) {
                aR[0][p] = r0; aR[1][p] = r1;
                aZ[0][p] = z0; aZ[1][p] = z1;
                aNi[0][p] = n0; aNi[1][p] = n1;
            }
        }
        const float4* w = g_WgP4 + t;          // stride per k2 = 3*256
        float4 wA[2][3], wB[2][3];
#pragma unroll
        for (int q = 0; q < 2; ++q)
#pragma unroll
            for (int g = 0; g < 3; ++g) wA[q][g] = w[(q * 3 + g) * 256];
        w += 2 * 3 * 256;

        {   // ih phase: 64 blocks (128 k2), f = xpT
            const float* f = xpT;
#pragma unroll 1
            for (int bb = 0; bb < 32; ++bb) {
#pragma unroll
                for (int q = 0; q < 2; ++q)
#pragma unroll
                    for (int g = 0; g < 3; ++g) wB[q][g] = w[(q * 3 + g) * 256];
                w += 1536;
                proc2(f, wA, aR, aZ, aNi);
#pragma unroll
                for (int q = 0; q < 2; ++q)
#pragma unroll
                    for (int g = 0; g < 3; ++g) wA[q][g] = w[(q * 3 + g) * 256];
                w += 1536;
                proc2(f, wB, aR, aZ, aNi);
            }
            // wA now holds block 64 = first hh block (combined array!)
        }
        {
            u64 n0 = splat2(bn_h0), n1 = splat2(bn_h1);
#pragma unroll
            for (int p = 0; p < 4; ++p) { aNh[0][p] = n0; aNh[1][p] = n1; }
        }
        {   // hh phase: 128 blocks (256 k2), f = featT (pad absorbs overrun)
            const float* f = featT;
#pragma unroll 1
            for (int bb = 0; bb < 64; ++bb) {
#pragma unroll
                for (int q = 0; q < 2; ++q)
#pragma unroll
                    for (int g = 0; g < 3; ++g) wB[q][g] = w[(q * 3 + g) * 256];
                w += 1536;
                proc2(f, wA, aR, aZ, aNh);
#pragma unroll
                for (int q = 0; q < 2; ++q)
#pragma unroll
                    for (int g = 0; g < 3; ++g) wA[q][g] = w[(q * 3 + g) * 256];
                w += 1536;
                proc2(f, wB, aR, aZ, aNh);
            }
        }

        // ---- gates + h_new (registers) ------------------------------------
        float hn[2][8];
#pragma unroll
        for (int cc = 0; cc < 2; ++cc) {
#pragma unroll
            for (int p = 0; p < 4; ++p) {
                float2 rr = unpack2(aR[cc][p]);
                float2 zz = unpack2(aZ[cc][p]);
                float2 ni = unpack2(aNi[cc][p]);
                float2 nh = unpack2(aNh[cc][p]);
                float rx = sigm(rr.x), ry = sigm(rr.y);
                float zx = sigm(zz.x), zy = sigm(zz.y);
                float nx = tanhf(ni.x + rx * nh.x);
                float ny = tanhf(ni.y + ry * nh.y);
                float hx = featT[(c0 + cc) * 8 + 2 * p];
                float hy = featT[(c0 + cc) * 8 + 2 * p + 1];
                hn[cc][2 * p]     = nx + zx * (hx - nx);   // (1-z)*n + z*h
                hn[cc][2 * p + 1] = ny + zy * (hy - ny);
            }
        }
        __syncthreads();   // everyone done reading old h
        *reinterpret_cast<float4*>(featT + c0 * 8) =
            make_float4(hn[0][0], hn[0][1], hn[0][2], hn[0][3]);
        *reinterpret_cast<float4*>(featT + c0 * 8 + 4) =
            make_float4(hn[0][4], hn[0][5], hn[0][6], hn[0][7]);
        *reinterpret_cast<float4*>(featT + c0 * 8 + 8) =
            make_float4(hn[1][0], hn[1][1], hn[1][2], hn[1][3]);
        *reinterpret_cast<float4*>(featT + c0 * 8 + 12) =
            make_float4(hn[1][4], hn[1][5], hn[1][6], hn[1][7]);

        do_heads(featT, red, out, b0, step + 1, bmu, blv);  // starts with sync
    }
}

// ---------------------------------------------------------------------------
extern "C" void kernel_launch(void* const* d_in, const int* in_sizes, int n_in,
                              void* d_out, int out_size) {
    const float* xl  = (const float*)d_in[0];   // x_l_seq   [1024,168,64]
    const float* xe  = (const float*)d_in[1];   // x_ext_seq [1024,168,16]
    const float* z   = (const float*)d_in[2];   // z_latent  [1024,512]
    const float* Wih = (const float*)d_in[3];   // [1536,256]
    const float* Whh = (const float*)d_in[4];   // [1536,512]
    const float* bih = (const float*)d_in[5];   // [1536]
    const float* bhh = (const float*)d_in[6];   // [1536]
    const float* Wmu = (const float*)d_in[7];   // [24,512]
    const float* bmu = (const float*)d_in[8];   // [24]
    const float* Wlv = (const float*)d_in[9];   // [24,512]
    const float* blv = (const float*)d_in[10];  // [24]
    const float* Wtb = (const float*)d_in[11];  // [592,256]
    const float* btb = (const float*)d_in[12];  // [256]
    float* out = (float*)d_out;                 // mu [1024,169,24] then lv

    prep_kernel<<<256, 256>>>(Wih, Whh, Wmu, Wlv, Wtb);
    decoder_kernel<<<NCTA, NT>>>(xl, xe, z, bih, bhh, bmu, blv, btb, out);
}